// round 15
// baseline (speedup 1.0000x reference)
#include <cuda_runtime.h>
#include <math.h>

#define T_STEPS 32768
#define HDIM 1024
#define H3 3072
#define NCTA 128
#define UNITS_PER_CTA 8   /* 1024 / 128 */
#define NCOPY 16          /* replica tables; 8 CTAs share one copy (measured optimum) */

/* ------------------------- scratch (device globals) ------------------------- */
__device__ float              g_WhT[(size_t)H3 * HDIM];       /* 12 MB transposed Wh */
__device__ float              g_A012[3 * H3];                 /* rank-2 gi projections */
/* mailbox: 2 parities x 16 copies x 1024 tagged pairs (8B) = 256 KB */
__device__ unsigned long long g_mbox[2 * NCOPY * HDIM];
__device__ float              g_hseq[(size_t)T_STEPS * HDIM]; /* 128 MB GRU outputs */
__device__ float              g_buf1[(size_t)T_STEPS * HDIM]; /* 128 MB ping */
__device__ float              g_buf2[(size_t)T_STEPS * HDIM]; /* 128 MB pong */
__device__ float              g_Wp[HDIM * 256];               /* packed head weights */
__device__ float              g_head[(size_t)T_STEPS * 256];  /* head GEMM out */

/* ------------------------------ prep kernels ------------------------------- */

/* Wh [1024, 3072] row-major -> WhT [3072, 1024] for coalesced per-column loads */
__global__ void transpose_wh(const float* __restrict__ Wh) {
    __shared__ float tile[32][33];
    int c0 = blockIdx.x * 32, i0 = blockIdx.y * 32;
    int tx = threadIdx.x, ty = threadIdx.y;      /* block (32, 8) */
    for (int r = ty; r < 32; r += 8)
        tile[r][tx] = Wh[(size_t)(i0 + r) * H3 + (c0 + tx)];
    __syncthreads();
    for (int r = ty; r < 32; r += 8)
        g_WhT[(size_t)(c0 + r) * HDIM + (i0 + tx)] = tile[tx][r];
}

/* A0 = W_in[0,:]@Wi ; A1 = W_in[1,:]@Wi ; A2 = b_in@Wi */
__global__ void a012_kernel(const float* __restrict__ W_in,
                            const float* __restrict__ b_in,
                            const float* __restrict__ Wi) {
    int c = blockIdx.x * 256 + threadIdx.x;
    if (c >= H3) return;
    float a0 = 0.f, a1 = 0.f, a2 = 0.f;
    for (int i = 0; i < HDIM; i++) {
        float w = Wi[(size_t)i * H3 + c];
        a0 = fmaf(W_in[i],        w, a0);
        a1 = fmaf(W_in[HDIM + i], w, a1);
        a2 = fmaf(b_in[i],        w, a2);
    }
    g_A012[c]          = a0;
    g_A012[H3 + c]     = a1;
    g_A012[2 * H3 + c] = a2;
}

/* pack amp/harm/noise weight columns into a single [1024, 256] matrix */
__global__ void pack_heads(const float* __restrict__ amp_W,
                           const float* __restrict__ harm_W,
                           const float* __restrict__ noise_W) {
    int idx = blockIdx.x * 256 + threadIdx.x;   /* grid 1024 -> 262144 */
    int k = idx >> 8, n = idx & 255;
    float v = 0.f;
    if (n == 0)        v = amp_W[k];
    else if (n <= 100) v = harm_W[k * 100 + (n - 1)];
    else if (n <= 165) v = noise_W[k * 65 + (n - 101)];
    g_Wp[idx] = v;
}

/* ----------------------------- math helpers -------------------------------- */
__device__ __forceinline__ void fma2(unsigned long long& acc,
                                     unsigned long long a, unsigned long long b) {
    asm("fma.rn.f32x2 %0, %1, %2, %0;" : "+l"(acc) : "l"(a), "l"(b));
}
__device__ __forceinline__ float sum2(unsigned long long v) {
    float lo, hi;
    asm("mov.b64 {%0, %1}, %2;" : "=f"(lo), "=f"(hi) : "l"(v));
    return lo + hi;
}
__device__ __forceinline__ float rcpa(float x) {
    float r;
    asm("rcp.approx.f32 %0, %1;" : "=f"(r) : "f"(x));
    return r;
}
__device__ __forceinline__ unsigned f2tf32(float x) {
    unsigned r;
    asm("cvt.rna.tf32.f32 %0, %1;" : "=r"(r) : "f"(x));
    return r;
}

/* --------------------------------- GRU -------------------------------------
 * Persistent kernel: 128 CTAs (1/SM), 256 threads. Warp w of CTA b owns unit
 * b*8+w; Wh columns live in registers (f32x2-packed), h lives in SMEM.
 * Protocol = R9/R13 empirical optimum (16 replicas, predicated 16-lane
 * publish, pre-poll barrier, fused detect+reload). Do not perturb.
 *
 * R15 delta: hseq is no longer written as 8 scattered 4B stores per CTA per
 * step in the publish window. Instead, a rotating owner CTA (t & 127) writes
 * the full coalesced 4KB row AFTER the poll reload (thread tid's reloaded
 * registers are exactly hseq[t][4*tid..4*tid+3] = h_{t+1}).
 * --------------------------------------------------------------------------- */
__global__ __launch_bounds__(256, 1)
void gru_kernel(const float* __restrict__ f0, const float* __restrict__ loud,
                const float* __restrict__ b_h, const float* __restrict__ h0) {
    __shared__ float h_s[HDIM];

    const int tid  = threadIdx.x;
    const int lane = tid & 31;
    const int warp = tid >> 5;
    const int unit = blockIdx.x * UNITS_PER_CTA + warp;
    const int cr = unit, cz = HDIM + unit, cn = 2 * HDIM + unit;
    const int mycopy = blockIdx.x >> 3;      /* 8 CTAs per replica */

    ulonglong2 wr2[8], wz2[8], wn2[8];
    {
        const ulonglong2* Wr = (const ulonglong2*)(g_WhT + (size_t)cr * HDIM);
        const ulonglong2* Wz = (const ulonglong2*)(g_WhT + (size_t)cz * HDIM);
        const ulonglong2* Wn = (const ulonglong2*)(g_WhT + (size_t)cn * HDIM);
#pragma unroll
        for (int j = 0; j < 8; j++) {
            wr2[j] = Wr[j * 32 + lane];
            wz2[j] = Wz[j * 32 + lane];
            wn2[j] = Wn[j * 32 + lane];
        }
    }
    const float br = b_h[cr], bz = b_h[cz], bn = b_h[cn];
    const float a0r = g_A012[cr], a1r = g_A012[H3 + cr], a2r = g_A012[2 * H3 + cr];
    const float a0z = g_A012[cz], a1z = g_A012[H3 + cz], a2z = g_A012[2 * H3 + cz];
    const float a0n = g_A012[cn], a1n = g_A012[H3 + cn], a2n = g_A012[2 * H3 + cn];

    for (int i = tid; i < HDIM; i += 256) h_s[i] = h0[i];
    __syncthreads();

    for (int t = 0; t < T_STEPS; t++) {
        const float ft = __ldg(f0 + t);
        const float lt = __ldg(loud + t);
        const float hp = h_s[unit];          /* prefetch own previous h early */

        unsigned long long ar = 0ull, az = 0ull, an = 0ull;
        const ulonglong2* h2 = (const ulonglong2*)h_s;
#pragma unroll
        for (int j = 0; j < 8; j++) {
            ulonglong2 hv = h2[j * 32 + lane];
            fma2(ar, hv.x, wr2[j].x); fma2(az, hv.x, wz2[j].x); fma2(an, hv.x, wn2[j].x);
            fma2(ar, hv.y, wr2[j].y); fma2(az, hv.y, wz2[j].y); fma2(an, hv.y, wn2[j].y);
        }
        float accr = sum2(ar), accz = sum2(az), accn = sum2(an);
#pragma unroll
        for (int off = 16; off; off >>= 1) {
            accr += __shfl_xor_sync(0xffffffffu, accr, off);
            accz += __shfl_xor_sync(0xffffffffu, accz, off);
            accn += __shfl_xor_sync(0xffffffffu, accn, off);
        }

        const unsigned tag = (unsigned)(t + 1);
        const int par = (t + 1) & 1;

        const float gir = fmaf(ft, a0r, fmaf(lt, a1r, a2r));
        const float giz = fmaf(ft, a0z, fmaf(lt, a1z, a2z));
        const float gin = fmaf(ft, a0n, fmaf(lt, a1n, a2n));
        const float xr = gir + accr + br;
        const float xz = giz + accz + bz;
        const float r  = rcpa(1.f + __expf(-xr));
        const float z  = rcpa(1.f + __expf(-xz));
        const float xn = gin + r * (accn + bn);
        const float a  = fabsf(xn);
        const float e  = __expf(-2.f * a);
        float th = (1.f - e) * rcpa(1.f + e);
        th = copysignf(th, xn);
        const float hn = (1.f - z) * th + z * hp;

        /* ---- immediate per-warp publish: one warp-wide 8B store, 16 lanes ---- */
        {
            const unsigned long long pv =
                ((unsigned long long)tag << 32) | (unsigned long long)__float_as_uint(hn);
            if (lane < NCOPY) {
                unsigned long long* dst = g_mbox + (size_t)par * NCOPY * HDIM
                                        + (size_t)lane * HDIM + unit;
                asm volatile("st.relaxed.gpu.global.u64 [%0], %1;"
                             :: "l"(dst), "l"(pv) : "memory");
            }
        }
        __syncthreads();   /* all warps done reading h_s; compress poll window */

        /* ---- fused detect + reload from my group's replica ---- */
        {
            const unsigned long long* rp = g_mbox + (size_t)par * NCOPY * HDIM
                                         + (size_t)mycopy * HDIM + tid * 4;
            unsigned long long v0, v1, v2, v3;
            while (true) {
                asm volatile("ld.relaxed.gpu.global.v2.u64 {%0,%1}, [%2];"
                             : "=l"(v0), "=l"(v1) : "l"(rp) : "memory");
                asm volatile("ld.relaxed.gpu.global.v2.u64 {%0,%1}, [%2];"
                             : "=l"(v2), "=l"(v3) : "l"(rp + 2) : "memory");
                if ((unsigned)(v0 >> 32) >= tag && (unsigned)(v1 >> 32) >= tag &&
                    (unsigned)(v2 >> 32) >= tag && (unsigned)(v3 >> 32) >= tag)
                    break;
            }
            float4 hv;
            hv.x = __uint_as_float((unsigned)v0);
            hv.y = __uint_as_float((unsigned)v1);
            hv.z = __uint_as_float((unsigned)v2);
            hv.w = __uint_as_float((unsigned)v3);
            ((float4*)h_s)[tid] = hv;

            /* rotating owner writes hseq[t] = h_{t+1}, fully coalesced */
            if (blockIdx.x == (t & (NCTA - 1)))
                *(float4*)(g_hseq + (size_t)t * HDIM + tid * 4) = hv;
        }
        __syncthreads();
    }
}

/* ----------------------- TF32 tensor-core GEMM -----------------------------
 * C[M,N] = A[M,K] @ B[K,N], fp32 in/out, tf32 mma.sync.m16n8k8 compute.
 * CTA tile 128x128x32, 8 warps in 2(M) x 4(N) grid, each warp 64x32 via
 * 4x4 m16n8k8 tiles per k-step. SMEM tiles k-major with 132-word row pad.
 * --------------------------------------------------------------------------- */
__global__ __launch_bounds__(256, 2)
void tf32gemm128(const float* __restrict__ A, const float* __restrict__ B,
                 float* __restrict__ C, int M, int N, int K) {
    __shared__ unsigned As[32][132];   /* [k][m], tf32 bits */
    __shared__ unsigned Bs[32][132];   /* [k][n], tf32 bits */

    const int tid  = threadIdx.x;
    const int lane = tid & 31;
    const int warp = tid >> 5;
    const int g    = lane >> 2;        /* 0..7 */
    const int tg   = lane & 3;         /* 0..3 */
    const int wm   = (warp & 1) * 64;
    const int wn   = (warp >> 1) * 32;
    const int bm   = blockIdx.y * 128;
    const int bn   = blockIdx.x * 128;

    const int arow  = tid >> 1;
    const int acol0 = (tid & 1) * 4;
    const int brow0 = tid >> 5;
    const int bcol  = (tid & 31) * 4;

    float c[4][4][4];
#pragma unroll
    for (int mt = 0; mt < 4; mt++)
#pragma unroll
        for (int nt = 0; nt < 4; nt++)
#pragma unroll
            for (int i = 0; i < 4; i++) c[mt][nt][i] = 0.f;

    for (int k0 = 0; k0 < K; k0 += 32) {
#pragma unroll
        for (int c4 = 0; c4 < 4; c4++) {
            const int kc = acol0 + c4 * 8;
            float4 av = *(const float4*)(A + (size_t)(bm + arow) * K + k0 + kc);
            As[kc + 0][arow] = f2tf32(av.x);
            As[kc + 1][arow] = f2tf32(av.y);
            As[kc + 2][arow] = f2tf32(av.z);
            As[kc + 3][arow] = f2tf32(av.w);
        }
#pragma unroll
        for (int r = 0; r < 4; r++) {
            const int kr = brow0 + r * 8;
            float4 bv = *(const float4*)(B + (size_t)(k0 + kr) * N + bn + bcol);
            Bs[kr][bcol + 0] = f2tf32(bv.x);
            Bs[kr][bcol + 1] = f2tf32(bv.y);
            Bs[kr][bcol + 2] = f2tf32(bv.z);
            Bs[kr][bcol + 3] = f2tf32(bv.w);
        }
        __syncthreads();

#pragma unroll
        for (int kk = 0; kk < 4; kk++) {
            const int kb = kk * 8;
            unsigned af[4][4], bf[4][2];
#pragma unroll
            for (int mt = 0; mt < 4; mt++) {
                const int m = wm + mt * 16 + g;
                af[mt][0] = As[kb + tg][m];
                af[mt][1] = As[kb + tg][m + 8];
                af[mt][2] = As[kb + tg + 4][m];
                af[mt][3] = As[kb + tg + 4][m + 8];
            }
#pragma unroll
            for (int nt = 0; nt < 4; nt++) {
                const int n = wn + nt * 8 + g;
                bf[nt][0] = Bs[kb + tg][n];
                bf[nt][1] = Bs[kb + tg + 4][n];
            }
#pragma unroll
            for (int mt = 0; mt < 4; mt++)
#pragma unroll
                for (int nt = 0; nt < 4; nt++) {
                    asm volatile(
                        "mma.sync.aligned.m16n8k8.row.col.f32.tf32.tf32.f32 "
                        "{%0,%1,%2,%3}, {%4,%5,%6,%7}, {%8,%9}, {%0,%1,%2,%3};"
                        : "+f"(c[mt][nt][0]), "+f"(c[mt][nt][1]),
                          "+f"(c[mt][nt][2]), "+f"(c[mt][nt][3])
                        : "r"(af[mt][0]), "r"(af[mt][1]),
                          "r"(af[mt][2]), "r"(af[mt][3]),
                          "r"(bf[nt][0]), "r"(bf[nt][1]));
                }
        }
        __syncthreads();
    }

#pragma unroll
    for (int mt = 0; mt < 4; mt++) {
        const int m = bm + wm + mt * 16 + g;
#pragma unroll
        for (int nt = 0; nt < 4; nt++) {
            const int n = bn + wn + nt * 8 + 2 * tg;
            float2 lo = make_float2(c[mt][nt][0], c[mt][nt][1]);
            float2 hi = make_float2(c[mt][nt][2], c[mt][nt][3]);
            *(float2*)(C + (size_t)m * N + n)       = lo;
            *(float2*)(C + (size_t)(m + 8) * N + n) = hi;
        }
    }
}

/* ------------------------------ fp32 SGEMM (heads) -------------------------- */
__global__ __launch_bounds__(256, 2)
void sgemm128(const float* __restrict__ A, const float* __restrict__ B,
              float* __restrict__ C, int M, int N, int K) {
    __shared__ float As[8][128];
    __shared__ float Bs[8][128];
    const int tid = threadIdx.x;
    const int bn = blockIdx.x, bm = blockIdx.y;
    const float* Ab = A + (size_t)bm * 128 * K;
    const float* Bb = B + (size_t)bn * 128;
    float* Cb = C + (size_t)bm * 128 * N + (size_t)bn * 128;
    const int arow = tid >> 1, acol = (tid & 1) * 4;
    const int brow = tid >> 5, bcol = (tid & 31) * 4;
    const int tm = (tid >> 4) * 8, tn = (tid & 15) * 8;

    float acc[8][8];
#pragma unroll
    for (int i = 0; i < 8; i++)
#pragma unroll
        for (int j = 0; j < 8; j++) acc[i][j] = 0.f;

    for (int k0 = 0; k0 < K; k0 += 8) {
        float4 av = *(const float4*)(Ab + (size_t)arow * K + k0 + acol);
        As[acol + 0][arow] = av.x;
        As[acol + 1][arow] = av.y;
        As[acol + 2][arow] = av.z;
        As[acol + 3][arow] = av.w;
        *(float4*)(&Bs[brow][bcol]) =
            *(const float4*)(Bb + (size_t)(k0 + brow) * N + bcol);
        __syncthreads();
#pragma unroll
        for (int k = 0; k < 8; k++) {
            float ra[8], rb[8];
#pragma unroll
            for (int i = 0; i < 8; i++) ra[i] = As[k][tm + i];
#pragma unroll
            for (int j = 0; j < 8; j++) rb[j] = Bs[k][tn + j];
#pragma unroll
            for (int i = 0; i < 8; i++)
#pragma unroll
                for (int j = 0; j < 8; j++)
                    acc[i][j] = fmaf(ra[i], rb[j], acc[i][j]);
        }
        __syncthreads();
    }
#pragma unroll
    for (int i = 0; i < 8; i++)
#pragma unroll
        for (int j = 0; j < 8; j += 4) {
            float4 v = make_float4(acc[i][j], acc[i][j + 1], acc[i][j + 2], acc[i][j + 3]);
            *(float4*)(Cb + (size_t)(tm + i) * N + tn + j) = v;
        }
}

/* --------------------------- LayerNorm + ReLU ------------------------------ */
__device__ __forceinline__ float block_reduce_sum_256(float v, float* red) {
#pragma unroll
    for (int off = 16; off; off >>= 1) v += __shfl_xor_sync(0xffffffffu, v, off);
    const int lane = threadIdx.x & 31, w = threadIdx.x >> 5;
    if (lane == 0) red[w] = v;
    __syncthreads();
    if (threadIdx.x < 32) {
        float r = (threadIdx.x < 8) ? red[threadIdx.x] : 0.f;
#pragma unroll
        for (int off = 4; off; off >>= 1) r += __shfl_xor_sync(0xffffffffu, r, off);
        if (threadIdx.x == 0) red[0] = r;
    }
    __syncthreads();
    float out = red[0];
    __syncthreads();
    return out;
}

__global__ __launch_bounds__(256)
void ln_relu_kernel(const float* __restrict__ X, const float* __restrict__ bias,
                    const float* __restrict__ scale, const float* __restrict__ beta,
                    float* __restrict__ Y) {
    __shared__ float red[8];
    const int row = blockIdx.x, tid = threadIdx.x;
    float4 x = ((const float4*)(X + (size_t)row * HDIM))[tid];
    float4 b = ((const float4*)bias)[tid];
    x.x += b.x; x.y += b.y; x.z += b.z; x.w += b.w;

    float s   = x.x + x.y + x.z + x.w;
    float mu  = block_reduce_sum_256(s, red) * (1.f / HDIM);
    float dx0 = x.x - mu, dx1 = x.y - mu, dx2 = x.z - mu, dx3 = x.w - mu;
    float sq  = dx0 * dx0 + dx1 * dx1 + dx2 * dx2 + dx3 * dx3;
    float var = block_reduce_sum_256(sq, red) * (1.f / HDIM);
    float inv = rsqrtf(var + 1e-6f);

    float4 g = ((const float4*)scale)[tid];
    float4 t = ((const float4*)beta)[tid];
    float4 y;
    y.x = fmaxf(fmaf(dx0 * inv, g.x, t.x), 0.f);
    y.y = fmaxf(fmaf(dx1 * inv, g.y, t.y), 0.f);
    y.z = fmaxf(fmaf(dx2 * inv, g.z, t.z), 0.f);
    y.w = fmaxf(fmaf(dx3 * inv, g.w, t.w), 0.f);
    ((float4*)(Y + (size_t)row * HDIM))[tid] = y;
}

/* ------------------------------ head epilogue ------------------------------ */
__device__ __forceinline__ float exp_sigmoid_f(float x) {
    float s = 1.f / (1.f + expf(-x));
    return 2.f * powf(s, 2.302585093f) + 1e-7f;
}

__global__ __launch_bounds__(128)
void head_epilogue(const float* __restrict__ head, const float* __restrict__ amp_b,
                   const float* __restrict__ harm_b, const float* __restrict__ noise_b,
                   float* __restrict__ out) {
    __shared__ float red[4];
    __shared__ float s_amp;
    const int row = blockIdx.x, tid = threadIdx.x;
    const float* hr = head + (size_t)row * 256;

    float myh = 0.f;
    if (tid < 100) myh = exp_sigmoid_f(hr[1 + tid] + harm_b[tid]);

    float s = myh;
#pragma unroll
    for (int off = 16; off; off >>= 1) s += __shfl_xor_sync(0xffffffffu, s, off);
    if ((tid & 31) == 0) red[tid >> 5] = s;
    __syncthreads();
    if (tid == 0) {
        float tot = red[0] + red[1] + red[2] + red[3];
        float amp = exp_sigmoid_f(hr[0] + amp_b[0]);
        s_amp = amp / (tot + 1e-8f);
    }
    __syncthreads();

    if (tid < 100)
        out[(size_t)row * 100 + tid] = s_amp * myh;
    if (tid < 65)
        out[(size_t)T_STEPS * 100 + (size_t)row * 65 + tid] = hr[101 + tid] + noise_b[tid];
}

/* -------------------------------- launcher --------------------------------- */
extern "C" void kernel_launch(void* const* d_in, const int* in_sizes, int n_in,
                              void* d_out, int out_size) {
    const float* f0       = (const float*)d_in[0];
    const float* loud     = (const float*)d_in[1];
    const float* W_in     = (const float*)d_in[2];
    const float* b_in     = (const float*)d_in[3];
    const float* Wi       = (const float*)d_in[4];
    const float* Wh       = (const float*)d_in[5];
    const float* b_h      = (const float*)d_in[6];
    const float* h0       = (const float*)d_in[7];
    const float* mlp_W    = (const float*)d_in[8];
    const float* mlp_b    = (const float*)d_in[9];
    const float* ln_scale = (const float*)d_in[10];
    const float* ln_bias  = (const float*)d_in[11];
    const float* amp_W    = (const float*)d_in[12];
    const float* amp_b    = (const float*)d_in[13];
    const float* harm_W   = (const float*)d_in[14];
    const float* harm_b   = (const float*)d_in[15];
    const float* noise_W  = (const float*)d_in[16];
    const float* noise_b  = (const float*)d_in[17];
    float* out = (float*)d_out;

    /* reset mailbox tags for graph-replay determinism */
    void* mbAddr = nullptr;
    cudaGetSymbolAddress(&mbAddr, g_mbox);
    cudaMemsetAsync(mbAddr, 0, 2 * NCOPY * HDIM * sizeof(unsigned long long), 0);

    float *hseq, *p1, *p2, *wp, *headb;
    cudaGetSymbolAddress((void**)&hseq,  g_hseq);
    cudaGetSymbolAddress((void**)&p1,    g_buf1);
    cudaGetSymbolAddress((void**)&p2,    g_buf2);
    cudaGetSymbolAddress((void**)&wp,    g_Wp);
    cudaGetSymbolAddress((void**)&headb, g_head);

    transpose_wh<<<dim3(96, 32), dim3(32, 8)>>>(Wh);
    a012_kernel<<<12, 256>>>(W_in, b_in, Wi);
    pack_heads<<<1024, 256>>>(amp_W, harm_W, noise_W);

    gru_kernel<<<NCTA, 256>>>(f0, loud, b_h, h0);

    /* MLP: 3 x (TF32 tensor GEMM -> LN+ReLU) */
    tf32gemm128<<<dim3(HDIM / 128, T_STEPS / 128), 256>>>(hseq, mlp_W, p1, T_STEPS, HDIM, HDIM);
    ln_relu_kernel<<<T_STEPS, 256>>>(p1, mlp_b, ln_scale, ln_bias, p2);

    tf32gemm128<<<dim3(HDIM / 128, T_STEPS / 128), 256>>>(p2, mlp_W + HDIM * HDIM, p1, T_STEPS, HDIM, HDIM);
    ln_relu_kernel<<<T_STEPS, 256>>>(p1, mlp_b + HDIM, ln_scale + HDIM, ln_bias + HDIM, p2);

    tf32gemm128<<<dim3(HDIM / 128, T_STEPS / 128), 256>>>(p2, mlp_W + 2 * HDIM * HDIM, p1, T_STEPS, HDIM, HDIM);
    ln_relu_kernel<<<T_STEPS, 256>>>(p1, mlp_b + 2 * HDIM, ln_scale + 2 * HDIM, ln_bias + 2 * HDIM, p2);

    /* heads: [T,1024] @ [1024,256(packed)] in fp32 for output precision */
    sgemm128<<<dim3(2, T_STEPS / 128), 256>>>(p2, wp, headb, T_STEPS, 256, HDIM);
    head_epilogue<<<T_STEPS, 128>>>(headb, amp_b, harm_b, noise_b, out);
}

// round 16
// speedup vs baseline: 1.0375x; 1.0375x over previous
#include <cuda_runtime.h>
#include <math.h>

#define T_STEPS 32768
#define HDIM 1024
#define H3 3072
#define NCTA 128
#define UNITS_PER_CTA 8   /* 1024 / 128 */
#define NCOPY 16          /* replica tables; 8 CTAs share one copy (measured optimum) */

/* ------------------------- scratch (device globals) ------------------------- */
__device__ float              g_WhT[(size_t)H3 * HDIM];       /* 12 MB transposed Wh */
__device__ float              g_A012[3 * H3];                 /* rank-2 gi projections */
/* mailbox: 2 parities x 16 copies x 1024 tagged pairs (8B) = 256 KB */
__device__ unsigned long long g_mbox[2 * NCOPY * HDIM];
__device__ float              g_hseq[(size_t)T_STEPS * HDIM]; /* 128 MB GRU outputs */
__device__ float              g_buf1[(size_t)T_STEPS * HDIM]; /* 128 MB ping */
__device__ float              g_buf2[(size_t)T_STEPS * HDIM]; /* 128 MB pong */
__device__ float              g_Wp[HDIM * 256];               /* packed head weights */
__device__ float              g_head[(size_t)T_STEPS * 256];  /* head GEMM out */

/* ------------------------------ prep kernels ------------------------------- */

/* Wh [1024, 3072] row-major -> WhT [3072, 1024] for coalesced per-column loads */
__global__ void transpose_wh(const float* __restrict__ Wh) {
    __shared__ float tile[32][33];
    int c0 = blockIdx.x * 32, i0 = blockIdx.y * 32;
    int tx = threadIdx.x, ty = threadIdx.y;      /* block (32, 8) */
    for (int r = ty; r < 32; r += 8)
        tile[r][tx] = Wh[(size_t)(i0 + r) * H3 + (c0 + tx)];
    __syncthreads();
    for (int r = ty; r < 32; r += 8)
        g_WhT[(size_t)(c0 + r) * HDIM + (i0 + tx)] = tile[tx][r];
}

/* A0 = W_in[0,:]@Wi ; A1 = W_in[1,:]@Wi ; A2 = b_in@Wi */
__global__ void a012_kernel(const float* __restrict__ W_in,
                            const float* __restrict__ b_in,
                            const float* __restrict__ Wi) {
    int c = blockIdx.x * 256 + threadIdx.x;
    if (c >= H3) return;
    float a0 = 0.f, a1 = 0.f, a2 = 0.f;
    for (int i = 0; i < HDIM; i++) {
        float w = Wi[(size_t)i * H3 + c];
        a0 = fmaf(W_in[i],        w, a0);
        a1 = fmaf(W_in[HDIM + i], w, a1);
        a2 = fmaf(b_in[i],        w, a2);
    }
    g_A012[c]          = a0;
    g_A012[H3 + c]     = a1;
    g_A012[2 * H3 + c] = a2;
}

/* pack amp/harm/noise weight columns into a single [1024, 256] matrix */
__global__ void pack_heads(const float* __restrict__ amp_W,
                           const float* __restrict__ harm_W,
                           const float* __restrict__ noise_W) {
    int idx = blockIdx.x * 256 + threadIdx.x;   /* grid 1024 -> 262144 */
    int k = idx >> 8, n = idx & 255;
    float v = 0.f;
    if (n == 0)        v = amp_W[k];
    else if (n <= 100) v = harm_W[k * 100 + (n - 1)];
    else if (n <= 165) v = noise_W[k * 65 + (n - 101)];
    g_Wp[idx] = v;
}

/* ----------------------------- math helpers -------------------------------- */
__device__ __forceinline__ void fma2(unsigned long long& acc,
                                     unsigned long long a, unsigned long long b) {
    asm("fma.rn.f32x2 %0, %1, %2, %0;" : "+l"(acc) : "l"(a), "l"(b));
}
__device__ __forceinline__ float sum2(unsigned long long v) {
    float lo, hi;
    asm("mov.b64 {%0, %1}, %2;" : "=f"(lo), "=f"(hi) : "l"(v));
    return lo + hi;
}
__device__ __forceinline__ float rcpa(float x) {
    float r;
    asm("rcp.approx.f32 %0, %1;" : "=f"(r) : "f"(x));
    return r;
}
__device__ __forceinline__ unsigned f2tf32(float x) {
    unsigned r;
    asm("cvt.rna.tf32.f32 %0, %1;" : "=r"(r) : "f"(x));
    return r;
}

/* --------------------------------- GRU -------------------------------------
 * Byte-exact R14 (proven 40.3 ms): 128 CTAs, 256 threads, unit = b*8+w,
 * Wh in registers (f32x2), h in SMEM. 16 replicas, predicated 16-lane
 * publish, lane0 scattered hseq store (fire-and-forget), pre-poll barrier,
 * fused detect+reload. Do not perturb — protocol space exhaustively mapped.
 * --------------------------------------------------------------------------- */
__global__ __launch_bounds__(256, 1)
void gru_kernel(const float* __restrict__ f0, const float* __restrict__ loud,
                const float* __restrict__ b_h, const float* __restrict__ h0) {
    __shared__ float h_s[HDIM];

    const int tid  = threadIdx.x;
    const int lane = tid & 31;
    const int warp = tid >> 5;
    const int unit = blockIdx.x * UNITS_PER_CTA + warp;
    const int cr = unit, cz = HDIM + unit, cn = 2 * HDIM + unit;
    const int mycopy = blockIdx.x >> 3;      /* 8 CTAs per replica */

    ulonglong2 wr2[8], wz2[8], wn2[8];
    {
        const ulonglong2* Wr = (const ulonglong2*)(g_WhT + (size_t)cr * HDIM);
        const ulonglong2* Wz = (const ulonglong2*)(g_WhT + (size_t)cz * HDIM);
        const ulonglong2* Wn = (const ulonglong2*)(g_WhT + (size_t)cn * HDIM);
#pragma unroll
        for (int j = 0; j < 8; j++) {
            wr2[j] = Wr[j * 32 + lane];
            wz2[j] = Wz[j * 32 + lane];
            wn2[j] = Wn[j * 32 + lane];
        }
    }
    const float br = b_h[cr], bz = b_h[cz], bn = b_h[cn];
    const float a0r = g_A012[cr], a1r = g_A012[H3 + cr], a2r = g_A012[2 * H3 + cr];
    const float a0z = g_A012[cz], a1z = g_A012[H3 + cz], a2z = g_A012[2 * H3 + cz];
    const float a0n = g_A012[cn], a1n = g_A012[H3 + cn], a2n = g_A012[2 * H3 + cn];

    for (int i = tid; i < HDIM; i += 256) h_s[i] = h0[i];
    __syncthreads();

    for (int t = 0; t < T_STEPS; t++) {
        const float ft = __ldg(f0 + t);
        const float lt = __ldg(loud + t);

        unsigned long long ar = 0ull, az = 0ull, an = 0ull;
        const ulonglong2* h2 = (const ulonglong2*)h_s;
#pragma unroll
        for (int j = 0; j < 8; j++) {
            ulonglong2 hv = h2[j * 32 + lane];
            fma2(ar, hv.x, wr2[j].x); fma2(az, hv.x, wz2[j].x); fma2(an, hv.x, wn2[j].x);
            fma2(ar, hv.y, wr2[j].y); fma2(az, hv.y, wz2[j].y); fma2(an, hv.y, wn2[j].y);
        }
        float accr = sum2(ar), accz = sum2(az), accn = sum2(an);
#pragma unroll
        for (int off = 16; off; off >>= 1) {
            accr += __shfl_xor_sync(0xffffffffu, accr, off);
            accz += __shfl_xor_sync(0xffffffffu, accz, off);
            accn += __shfl_xor_sync(0xffffffffu, accn, off);
        }

        const unsigned tag = (unsigned)(t + 1);
        const int par = (t + 1) & 1;

        const float gir = fmaf(ft, a0r, fmaf(lt, a1r, a2r));
        const float giz = fmaf(ft, a0z, fmaf(lt, a1z, a2z));
        const float gin = fmaf(ft, a0n, fmaf(lt, a1n, a2n));
        const float xr = gir + accr + br;
        const float xz = giz + accz + bz;
        const float r  = rcpa(1.f + __expf(-xr));
        const float z  = rcpa(1.f + __expf(-xz));
        const float xn = gin + r * (accn + bn);
        const float a  = fabsf(xn);
        const float e  = __expf(-2.f * a);
        float th = (1.f - e) * rcpa(1.f + e);
        th = copysignf(th, xn);
        const float hp = h_s[unit];
        const float hn = (1.f - z) * th + z * hp;

        {
            const unsigned long long pv =
                ((unsigned long long)tag << 32) | (unsigned long long)__float_as_uint(hn);
            if (lane < NCOPY) {
                unsigned long long* dst = g_mbox + (size_t)par * NCOPY * HDIM
                                        + (size_t)lane * HDIM + unit;
                asm volatile("st.relaxed.gpu.global.u64 [%0], %1;"
                             :: "l"(dst), "l"(pv) : "memory");
            }
            if (lane == 0) g_hseq[(size_t)t * HDIM + unit] = hn;
        }
        __syncthreads();

        {
            const unsigned long long* rp = g_mbox + (size_t)par * NCOPY * HDIM
                                         + (size_t)mycopy * HDIM + tid * 4;
            unsigned long long v0, v1, v2, v3;
            while (true) {
                asm volatile("ld.relaxed.gpu.global.v2.u64 {%0,%1}, [%2];"
                             : "=l"(v0), "=l"(v1) : "l"(rp) : "memory");
                asm volatile("ld.relaxed.gpu.global.v2.u64 {%0,%1}, [%2];"
                             : "=l"(v2), "=l"(v3) : "l"(rp + 2) : "memory");
                if ((unsigned)(v0 >> 32) >= tag && (unsigned)(v1 >> 32) >= tag &&
                    (unsigned)(v2 >> 32) >= tag && (unsigned)(v3 >> 32) >= tag)
                    break;
            }
            float4 hv;
            hv.x = __uint_as_float((unsigned)v0);
            hv.y = __uint_as_float((unsigned)v1);
            hv.z = __uint_as_float((unsigned)v2);
            hv.w = __uint_as_float((unsigned)v3);
            ((float4*)h_s)[tid] = hv;
        }
        __syncthreads();
    }
}

/* ----------------------- TF32 tensor-core GEMM (pipelined) ------------------
 * C[M,N] = A[M,K] @ B[K,N], fp32 in/out, tf32 mma.sync.m16n8k8 compute.
 * CTA tile 128x128x32, 8 warps 2(M)x4(N), warp 64x32. Register-prefetch
 * double buffer: while MMAs consume SMEM tile k, the next tile's float4s
 * are already in flight to registers; store-convert after the sync.
 * --------------------------------------------------------------------------- */
__global__ __launch_bounds__(256)
void tf32gemm128(const float* __restrict__ A, const float* __restrict__ B,
                 float* __restrict__ C, int M, int N, int K) {
    __shared__ unsigned As[32][132];   /* [k][m], tf32 bits */
    __shared__ unsigned Bs[32][132];   /* [k][n], tf32 bits */

    const int tid  = threadIdx.x;
    const int lane = tid & 31;
    const int warp = tid >> 5;
    const int g    = lane >> 2;
    const int tg   = lane & 3;
    const int wm   = (warp & 1) * 64;
    const int wn   = (warp >> 1) * 32;
    const int bm   = blockIdx.y * 128;
    const int bn   = blockIdx.x * 128;

    const int arow  = tid >> 1;
    const int acol0 = (tid & 1) * 4;
    const int brow0 = tid >> 5;
    const int bcol  = (tid & 31) * 4;

    float c[4][4][4];
#pragma unroll
    for (int mt = 0; mt < 4; mt++)
#pragma unroll
        for (int nt = 0; nt < 4; nt++)
#pragma unroll
            for (int i = 0; i < 4; i++) c[mt][nt][i] = 0.f;

    float4 avp[4], bvp[4];

    /* prologue: fetch tile k0=0 into registers */
#pragma unroll
    for (int c4 = 0; c4 < 4; c4++)
        avp[c4] = *(const float4*)(A + (size_t)(bm + arow) * K + acol0 + c4 * 8);
#pragma unroll
    for (int r = 0; r < 4; r++)
        bvp[r] = *(const float4*)(B + (size_t)(brow0 + r * 8) * N + bn + bcol);

    for (int k0 = 0; k0 < K; k0 += 32) {
        /* store current registers to SMEM (with tf32 convert) */
#pragma unroll
        for (int c4 = 0; c4 < 4; c4++) {
            const int kc = acol0 + c4 * 8;
            As[kc + 0][arow] = f2tf32(avp[c4].x);
            As[kc + 1][arow] = f2tf32(avp[c4].y);
            As[kc + 2][arow] = f2tf32(avp[c4].z);
            As[kc + 3][arow] = f2tf32(avp[c4].w);
        }
#pragma unroll
        for (int r = 0; r < 4; r++) {
            const int kr = brow0 + r * 8;
            Bs[kr][bcol + 0] = f2tf32(bvp[r].x);
            Bs[kr][bcol + 1] = f2tf32(bvp[r].y);
            Bs[kr][bcol + 2] = f2tf32(bvp[r].z);
            Bs[kr][bcol + 3] = f2tf32(bvp[r].w);
        }
        __syncthreads();

        /* prefetch NEXT tile into registers (overlaps with MMAs below) */
        const int k1 = k0 + 32;
        if (k1 < K) {
#pragma unroll
            for (int c4 = 0; c4 < 4; c4++)
                avp[c4] = *(const float4*)(A + (size_t)(bm + arow) * K + k1 + acol0 + c4 * 8);
#pragma unroll
            for (int r = 0; r < 4; r++)
                bvp[r] = *(const float4*)(B + (size_t)(k1 + brow0 + r * 8) * N + bn + bcol);
        }

#pragma unroll
        for (int kk = 0; kk < 4; kk++) {
            const int kb = kk * 8;
            unsigned af[4][4], bf[4][2];
#pragma unroll
            for (int mt = 0; mt < 4; mt++) {
                const int m = wm + mt * 16 + g;
                af[mt][0] = As[kb + tg][m];
                af[mt][1] = As[kb + tg][m + 8];
                af[mt][2] = As[kb + tg + 4][m];
                af[mt][3] = As[kb + tg + 4][m + 8];
            }
#pragma unroll
            for (int nt = 0; nt < 4; nt++) {
                const int n = wn + nt * 8 + g;
                bf[nt][0] = Bs[kb + tg][n];
                bf[nt][1] = Bs[kb + tg + 4][n];
            }
#pragma unroll
            for (int mt = 0; mt < 4; mt++)
#pragma unroll
                for (int nt = 0; nt < 4; nt++) {
                    asm volatile(
                        "mma.sync.aligned.m16n8k8.row.col.f32.tf32.tf32.f32 "
                        "{%0,%1,%2,%3}, {%4,%5,%6,%7}, {%8,%9}, {%0,%1,%2,%3};"
                        : "+f"(c[mt][nt][0]), "+f"(c[mt][nt][1]),
                          "+f"(c[mt][nt][2]), "+f"(c[mt][nt][3])
                        : "r"(af[mt][0]), "r"(af[mt][1]),
                          "r"(af[mt][2]), "r"(af[mt][3]),
                          "r"(bf[nt][0]), "r"(bf[nt][1]));
                }
        }
        __syncthreads();
    }

#pragma unroll
    for (int mt = 0; mt < 4; mt++) {
        const int m = bm + wm + mt * 16 + g;
#pragma unroll
        for (int nt = 0; nt < 4; nt++) {
            const int n = bn + wn + nt * 8 + 2 * tg;
            float2 lo = make_float2(c[mt][nt][0], c[mt][nt][1]);
            float2 hi = make_float2(c[mt][nt][2], c[mt][nt][3]);
            *(float2*)(C + (size_t)m * N + n)       = lo;
            *(float2*)(C + (size_t)(m + 8) * N + n) = hi;
        }
    }
}

/* ------------------------------ fp32 SGEMM (heads) -------------------------- */
__global__ __launch_bounds__(256, 2)
void sgemm128(const float* __restrict__ A, const float* __restrict__ B,
              float* __restrict__ C, int M, int N, int K) {
    __shared__ float As[8][128];
    __shared__ float Bs[8][128];
    const int tid = threadIdx.x;
    const int bn = blockIdx.x, bm = blockIdx.y;
    const float* Ab = A + (size_t)bm * 128 * K;
    const float* Bb = B + (size_t)bn * 128;
    float* Cb = C + (size_t)bm * 128 * N + (size_t)bn * 128;
    const int arow = tid >> 1, acol = (tid & 1) * 4;
    const int brow = tid >> 5, bcol = (tid & 31) * 4;
    const int tm = (tid >> 4) * 8, tn = (tid & 15) * 8;

    float acc[8][8];
#pragma unroll
    for (int i = 0; i < 8; i++)
#pragma unroll
        for (int j = 0; j < 8; j++) acc[i][j] = 0.f;

    for (int k0 = 0; k0 < K; k0 += 8) {
        float4 av = *(const float4*)(Ab + (size_t)arow * K + k0 + acol);
        As[acol + 0][arow] = av.x;
        As[acol + 1][arow] = av.y;
        As[acol + 2][arow] = av.z;
        As[acol + 3][arow] = av.w;
        *(float4*)(&Bs[brow][bcol]) =
            *(const float4*)(Bb + (size_t)(k0 + brow) * N + bcol);
        __syncthreads();
#pragma unroll
        for (int k = 0; k < 8; k++) {
            float ra[8], rb[8];
#pragma unroll
            for (int i = 0; i < 8; i++) ra[i] = As[k][tm + i];
#pragma unroll
            for (int j = 0; j < 8; j++) rb[j] = Bs[k][tn + j];
#pragma unroll
            for (int i = 0; i < 8; i++)
#pragma unroll
                for (int j = 0; j < 8; j++)
                    acc[i][j] = fmaf(ra[i], rb[j], acc[i][j]);
        }
        __syncthreads();
    }
#pragma unroll
    for (int i = 0; i < 8; i++)
#pragma unroll
        for (int j = 0; j < 8; j += 4) {
            float4 v = make_float4(acc[i][j], acc[i][j + 1], acc[i][j + 2], acc[i][j + 3]);
            *(float4*)(Cb + (size_t)(tm + i) * N + tn + j) = v;
        }
}

/* --------------------------- LayerNorm + ReLU ------------------------------ */
__device__ __forceinline__ float block_reduce_sum_256(float v, float* red) {
#pragma unroll
    for (int off = 16; off; off >>= 1) v += __shfl_xor_sync(0xffffffffu, v, off);
    const int lane = threadIdx.x & 31, w = threadIdx.x >> 5;
    if (lane == 0) red[w] = v;
    __syncthreads();
    if (threadIdx.x < 32) {
        float r = (threadIdx.x < 8) ? red[threadIdx.x] : 0.f;
#pragma unroll
        for (int off = 4; off; off >>= 1) r += __shfl_xor_sync(0xffffffffu, r, off);
        if (threadIdx.x == 0) red[0] = r;
    }
    __syncthreads();
    float out = red[0];
    __syncthreads();
    return out;
}

__global__ __launch_bounds__(256)
void ln_relu_kernel(const float* __restrict__ X, const float* __restrict__ bias,
                    const float* __restrict__ scale, const float* __restrict__ beta,
                    float* __restrict__ Y) {
    __shared__ float red[8];
    const int row = blockIdx.x, tid = threadIdx.x;
    float4 x = ((const float4*)(X + (size_t)row * HDIM))[tid];
    float4 b = ((const float4*)bias)[tid];
    x.x += b.x; x.y += b.y; x.z += b.z; x.w += b.w;

    float s   = x.x + x.y + x.z + x.w;
    float mu  = block_reduce_sum_256(s, red) * (1.f / HDIM);
    float dx0 = x.x - mu, dx1 = x.y - mu, dx2 = x.z - mu, dx3 = x.w - mu;
    float sq  = dx0 * dx0 + dx1 * dx1 + dx2 * dx2 + dx3 * dx3;
    float var = block_reduce_sum_256(sq, red) * (1.f / HDIM);
    float inv = rsqrtf(var + 1e-6f);

    float4 g = ((const float4*)scale)[tid];
    float4 t = ((const float4*)beta)[tid];
    float4 y;
    y.x = fmaxf(fmaf(dx0 * inv, g.x, t.x), 0.f);
    y.y = fmaxf(fmaf(dx1 * inv, g.y, t.y), 0.f);
    y.z = fmaxf(fmaf(dx2 * inv, g.z, t.z), 0.f);
    y.w = fmaxf(fmaf(dx3 * inv, g.w, t.w), 0.f);
    ((float4*)(Y + (size_t)row * HDIM))[tid] = y;
}

/* ------------------------------ head epilogue ------------------------------ */
__device__ __forceinline__ float exp_sigmoid_f(float x) {
    float s = 1.f / (1.f + expf(-x));
    return 2.f * powf(s, 2.302585093f) + 1e-7f;
}

__global__ __launch_bounds__(128)
void head_epilogue(const float* __restrict__ head, const float* __restrict__ amp_b,
                   const float* __restrict__ harm_b, const float* __restrict__ noise_b,
                   float* __restrict__ out) {
    __shared__ float red[4];
    __shared__ float s_amp;
    const int row = blockIdx.x, tid = threadIdx.x;
    const float* hr = head + (size_t)row * 256;

    float myh = 0.f;
    if (tid < 100) myh = exp_sigmoid_f(hr[1 + tid] + harm_b[tid]);

    float s = myh;
#pragma unroll
    for (int off = 16; off; off >>= 1) s += __shfl_xor_sync(0xffffffffu, s, off);
    if ((tid & 31) == 0) red[tid >> 5] = s;
    __syncthreads();
    if (tid == 0) {
        float tot = red[0] + red[1] + red[2] + red[3];
        float amp = exp_sigmoid_f(hr[0] + amp_b[0]);
        s_amp = amp / (tot + 1e-8f);
    }
    __syncthreads();

    if (tid < 100)
        out[(size_t)row * 100 + tid] = s_amp * myh;
    if (tid < 65)
        out[(size_t)T_STEPS * 100 + (size_t)row * 65 + tid] = hr[101 + tid] + noise_b[tid];
}

/* -------------------------------- launcher --------------------------------- */
extern "C" void kernel_launch(void* const* d_in, const int* in_sizes, int n_in,
                              void* d_out, int out_size) {
    const float* f0       = (const float*)d_in[0];
    const float* loud     = (const float*)d_in[1];
    const float* W_in     = (const float*)d_in[2];
    const float* b_in     = (const float*)d_in[3];
    const float* Wi       = (const float*)d_in[4];
    const float* Wh       = (const float*)d_in[5];
    const float* b_h      = (const float*)d_in[6];
    const float* h0       = (const float*)d_in[7];
    const float* mlp_W    = (const float*)d_in[8];
    const float* mlp_b    = (const float*)d_in[9];
    const float* ln_scale = (const float*)d_in[10];
    const float* ln_bias  = (const float*)d_in[11];
    const float* amp_W    = (const float*)d_in[12];
    const float* amp_b    = (const float*)d_in[13];
    const float* harm_W   = (const float*)d_in[14];
    const float* harm_b   = (const float*)d_in[15];
    const float* noise_W  = (const float*)d_in[16];
    const float* noise_b  = (const float*)d_in[17];
    float* out = (float*)d_out;

    /* reset mailbox tags for graph-replay determinism */
    void* mbAddr = nullptr;
    cudaGetSymbolAddress(&mbAddr, g_mbox);
    cudaMemsetAsync(mbAddr, 0, 2 * NCOPY * HDIM * sizeof(unsigned long long), 0);

    float *hseq, *p1, *p2, *wp, *headb;
    cudaGetSymbolAddress((void**)&hseq,  g_hseq);
    cudaGetSymbolAddress((void**)&p1,    g_buf1);
    cudaGetSymbolAddress((void**)&p2,    g_buf2);
    cudaGetSymbolAddress((void**)&wp,    g_Wp);
    cudaGetSymbolAddress((void**)&headb, g_head);

    transpose_wh<<<dim3(96, 32), dim3(32, 8)>>>(Wh);
    a012_kernel<<<12, 256>>>(W_in, b_in, Wi);
    pack_heads<<<1024, 256>>>(amp_W, harm_W, noise_W);

    gru_kernel<<<NCTA, 256>>>(f0, loud, b_h, h0);

    /* MLP: 3 x (TF32 tensor GEMM -> LN+ReLU) */
    tf32gemm128<<<dim3(HDIM / 128, T_STEPS / 128), 256>>>(hseq, mlp_W, p1, T_STEPS, HDIM, HDIM);
    ln_relu_kernel<<<T_STEPS, 256>>>(p1, mlp_b, ln_scale, ln_bias, p2);

    tf32gemm128<<<dim3(HDIM / 128, T_STEPS / 128), 256>>>(p2, mlp_W + HDIM * HDIM, p1, T_STEPS, HDIM, HDIM);
    ln_relu_kernel<<<T_STEPS, 256>>>(p1, mlp_b + HDIM, ln_scale + HDIM, ln_bias + HDIM, p2);

    tf32gemm128<<<dim3(HDIM / 128, T_STEPS / 128), 256>>>(p2, mlp_W + 2 * HDIM * HDIM, p1, T_STEPS, HDIM, HDIM);
    ln_relu_kernel<<<T_STEPS, 256>>>(p1, mlp_b + 2 * HDIM, ln_scale + 2 * HDIM, ln_bias + 2 * HDIM, p2);

    /* heads: [T,1024] @ [1024,256(packed)] in fp32 for output precision */
    sgemm128<<<dim3(2, T_STEPS / 128), 256>>>(p2, wp, headb, T_STEPS, 256, HDIM);
    head_epilogue<<<T_STEPS, 128>>>(headb, amp_b, harm_b, noise_b, out);
}

// round 17
// speedup vs baseline: 1.0436x; 1.0059x over previous
#include <cuda_runtime.h>
#include <math.h>

#define T_STEPS 32768
#define HDIM 1024
#define H3 3072
#define NCTA 128
#define UNITS_PER_CTA 8   /* 1024 / 128 */
#define NCOPY 16          /* replica tables; 8 CTAs share one copy (measured optimum) */

/* ------------------------- scratch (device globals) ------------------------- */
__device__ float              g_WhT[(size_t)H3 * HDIM];       /* 12 MB transposed Wh */
__device__ float              g_A012[3 * H3];                 /* rank-2 gi projections */
/* mailbox: 2 parities x 16 copies x 1024 tagged pairs (8B) = 256 KB */
__device__ unsigned long long g_mbox[2 * NCOPY * HDIM];
__device__ float              g_hseq[(size_t)T_STEPS * HDIM]; /* 128 MB GRU outputs */
__device__ float              g_buf1[(size_t)T_STEPS * HDIM]; /* 128 MB ping */
__device__ float              g_buf2[(size_t)T_STEPS * HDIM]; /* 128 MB pong */
__device__ float              g_Wp[HDIM * 256];               /* packed head weights */
__device__ float              g_head[(size_t)T_STEPS * 256];  /* head GEMM out */

/* ------------------------------ prep kernels ------------------------------- */

/* Wh [1024, 3072] row-major -> WhT [3072, 1024] for coalesced per-column loads */
__global__ void transpose_wh(const float* __restrict__ Wh) {
    __shared__ float tile[32][33];
    int c0 = blockIdx.x * 32, i0 = blockIdx.y * 32;
    int tx = threadIdx.x, ty = threadIdx.y;      /* block (32, 8) */
    for (int r = ty; r < 32; r += 8)
        tile[r][tx] = Wh[(size_t)(i0 + r) * H3 + (c0 + tx)];
    __syncthreads();
    for (int r = ty; r < 32; r += 8)
        g_WhT[(size_t)(c0 + r) * HDIM + (i0 + tx)] = tile[tx][r];
}

/* A0 = W_in[0,:]@Wi ; A1 = W_in[1,:]@Wi ; A2 = b_in@Wi */
__global__ void a012_kernel(const float* __restrict__ W_in,
                            const float* __restrict__ b_in,
                            const float* __restrict__ Wi) {
    int c = blockIdx.x * 256 + threadIdx.x;
    if (c >= H3) return;
    float a0 = 0.f, a1 = 0.f, a2 = 0.f;
    for (int i = 0; i < HDIM; i++) {
        float w = Wi[(size_t)i * H3 + c];
        a0 = fmaf(W_in[i],        w, a0);
        a1 = fmaf(W_in[HDIM + i], w, a1);
        a2 = fmaf(b_in[i],        w, a2);
    }
    g_A012[c]          = a0;
    g_A012[H3 + c]     = a1;
    g_A012[2 * H3 + c] = a2;
}

/* pack amp/harm/noise weight columns into a single [1024, 256] matrix */
__global__ void pack_heads(const float* __restrict__ amp_W,
                           const float* __restrict__ harm_W,
                           const float* __restrict__ noise_W) {
    int idx = blockIdx.x * 256 + threadIdx.x;   /* grid 1024 -> 262144 */
    int k = idx >> 8, n = idx & 255;
    float v = 0.f;
    if (n == 0)        v = amp_W[k];
    else if (n <= 100) v = harm_W[k * 100 + (n - 1)];
    else if (n <= 165) v = noise_W[k * 65 + (n - 101)];
    g_Wp[idx] = v;
}

/* ----------------------------- math helpers -------------------------------- */
__device__ __forceinline__ void fma2(unsigned long long& acc,
                                     unsigned long long a, unsigned long long b) {
    asm("fma.rn.f32x2 %0, %1, %2, %0;" : "+l"(acc) : "l"(a), "l"(b));
}
__device__ __forceinline__ float sum2(unsigned long long v) {
    float lo, hi;
    asm("mov.b64 {%0, %1}, %2;" : "=f"(lo), "=f"(hi) : "l"(v));
    return lo + hi;
}
__device__ __forceinline__ float rcpa(float x) {
    float r;
    asm("rcp.approx.f32 %0, %1;" : "=f"(r) : "f"(x));
    return r;
}
__device__ __forceinline__ unsigned f2tf32(float x) {
    unsigned r;
    asm("cvt.rna.tf32.f32 %0, %1;" : "=r"(r) : "f"(x));
    return r;
}

/* --------------------------------- GRU -------------------------------------
 * Byte-exact R14/R16 (proven 40.2 ms): 128 CTAs, 256 threads, unit = b*8+w,
 * Wh in registers (f32x2), h in SMEM. 16 replicas, predicated 16-lane
 * publish, lane0 scattered hseq store (fire-and-forget), pre-poll barrier,
 * fused detect+reload. FROZEN — protocol space exhaustively mapped.
 * --------------------------------------------------------------------------- */
__global__ __launch_bounds__(256, 1)
void gru_kernel(const float* __restrict__ f0, const float* __restrict__ loud,
                const float* __restrict__ b_h, const float* __restrict__ h0) {
    __shared__ float h_s[HDIM];

    const int tid  = threadIdx.x;
    const int lane = tid & 31;
    const int warp = tid >> 5;
    const int unit = blockIdx.x * UNITS_PER_CTA + warp;
    const int cr = unit, cz = HDIM + unit, cn = 2 * HDIM + unit;
    const int mycopy = blockIdx.x >> 3;      /* 8 CTAs per replica */

    ulonglong2 wr2[8], wz2[8], wn2[8];
    {
        const ulonglong2* Wr = (const ulonglong2*)(g_WhT + (size_t)cr * HDIM);
        const ulonglong2* Wz = (const ulonglong2*)(g_WhT + (size_t)cz * HDIM);
        const ulonglong2* Wn = (const ulonglong2*)(g_WhT + (size_t)cn * HDIM);
#pragma unroll
        for (int j = 0; j < 8; j++) {
            wr2[j] = Wr[j * 32 + lane];
            wz2[j] = Wz[j * 32 + lane];
            wn2[j] = Wn[j * 32 + lane];
        }
    }
    const float br = b_h[cr], bz = b_h[cz], bn = b_h[cn];
    const float a0r = g_A012[cr], a1r = g_A012[H3 + cr], a2r = g_A012[2 * H3 + cr];
    const float a0z = g_A012[cz], a1z = g_A012[H3 + cz], a2z = g_A012[2 * H3 + cz];
    const float a0n = g_A012[cn], a1n = g_A012[H3 + cn], a2n = g_A012[2 * H3 + cn];

    for (int i = tid; i < HDIM; i += 256) h_s[i] = h0[i];
    __syncthreads();

    for (int t = 0; t < T_STEPS; t++) {
        const float ft = __ldg(f0 + t);
        const float lt = __ldg(loud + t);

        unsigned long long ar = 0ull, az = 0ull, an = 0ull;
        const ulonglong2* h2 = (const ulonglong2*)h_s;
#pragma unroll
        for (int j = 0; j < 8; j++) {
            ulonglong2 hv = h2[j * 32 + lane];
            fma2(ar, hv.x, wr2[j].x); fma2(az, hv.x, wz2[j].x); fma2(an, hv.x, wn2[j].x);
            fma2(ar, hv.y, wr2[j].y); fma2(az, hv.y, wz2[j].y); fma2(an, hv.y, wn2[j].y);
        }
        float accr = sum2(ar), accz = sum2(az), accn = sum2(an);
#pragma unroll
        for (int off = 16; off; off >>= 1) {
            accr += __shfl_xor_sync(0xffffffffu, accr, off);
            accz += __shfl_xor_sync(0xffffffffu, accz, off);
            accn += __shfl_xor_sync(0xffffffffu, accn, off);
        }

        const unsigned tag = (unsigned)(t + 1);
        const int par = (t + 1) & 1;

        const float gir = fmaf(ft, a0r, fmaf(lt, a1r, a2r));
        const float giz = fmaf(ft, a0z, fmaf(lt, a1z, a2z));
        const float gin = fmaf(ft, a0n, fmaf(lt, a1n, a2n));
        const float xr = gir + accr + br;
        const float xz = giz + accz + bz;
        const float r  = rcpa(1.f + __expf(-xr));
        const float z  = rcpa(1.f + __expf(-xz));
        const float xn = gin + r * (accn + bn);
        const float a  = fabsf(xn);
        const float e  = __expf(-2.f * a);
        float th = (1.f - e) * rcpa(1.f + e);
        th = copysignf(th, xn);
        const float hp = h_s[unit];
        const float hn = (1.f - z) * th + z * hp;

        {
            const unsigned long long pv =
                ((unsigned long long)tag << 32) | (unsigned long long)__float_as_uint(hn);
            if (lane < NCOPY) {
                unsigned long long* dst = g_mbox + (size_t)par * NCOPY * HDIM
                                        + (size_t)lane * HDIM + unit;
                asm volatile("st.relaxed.gpu.global.u64 [%0], %1;"
                             :: "l"(dst), "l"(pv) : "memory");
            }
            if (lane == 0) g_hseq[(size_t)t * HDIM + unit] = hn;
        }
        __syncthreads();

        {
            const unsigned long long* rp = g_mbox + (size_t)par * NCOPY * HDIM
                                         + (size_t)mycopy * HDIM + tid * 4;
            unsigned long long v0, v1, v2, v3;
            while (true) {
                asm volatile("ld.relaxed.gpu.global.v2.u64 {%0,%1}, [%2];"
                             : "=l"(v0), "=l"(v1) : "l"(rp) : "memory");
                asm volatile("ld.relaxed.gpu.global.v2.u64 {%0,%1}, [%2];"
                             : "=l"(v2), "=l"(v3) : "l"(rp + 2) : "memory");
                if ((unsigned)(v0 >> 32) >= tag && (unsigned)(v1 >> 32) >= tag &&
                    (unsigned)(v2 >> 32) >= tag && (unsigned)(v3 >> 32) >= tag)
                    break;
            }
            float4 hv;
            hv.x = __uint_as_float((unsigned)v0);
            hv.y = __uint_as_float((unsigned)v1);
            hv.z = __uint_as_float((unsigned)v2);
            hv.w = __uint_as_float((unsigned)v3);
            ((float4*)h_s)[tid] = hv;
        }
        __syncthreads();
    }
}

/* ----------------------- TF32 tensor-core GEMM (pipelined) ------------------
 * C[M,N] = A[M,K] @ B[K,N], fp32 in/out, tf32 mma.sync.m16n8k8 compute.
 * CTA tile 128x128x32, 8 warps 2(M)x4(N), warp 64x32. Register-prefetch
 * double buffer hides global-load latency behind the MMAs.
 * Used for the 3 MLP GEMMs AND the heads GEMM (N=256 is a multiple of 128).
 * --------------------------------------------------------------------------- */
__global__ __launch_bounds__(256)
void tf32gemm128(const float* __restrict__ A, const float* __restrict__ B,
                 float* __restrict__ C, int M, int N, int K) {
    __shared__ unsigned As[32][132];   /* [k][m], tf32 bits */
    __shared__ unsigned Bs[32][132];   /* [k][n], tf32 bits */

    const int tid  = threadIdx.x;
    const int lane = tid & 31;
    const int warp = tid >> 5;
    const int g    = lane >> 2;
    const int tg   = lane & 3;
    const int wm   = (warp & 1) * 64;
    const int wn   = (warp >> 1) * 32;
    const int bm   = blockIdx.y * 128;
    const int bn   = blockIdx.x * 128;

    const int arow  = tid >> 1;
    const int acol0 = (tid & 1) * 4;
    const int brow0 = tid >> 5;
    const int bcol  = (tid & 31) * 4;

    float c[4][4][4];
#pragma unroll
    for (int mt = 0; mt < 4; mt++)
#pragma unroll
        for (int nt = 0; nt < 4; nt++)
#pragma unroll
            for (int i = 0; i < 4; i++) c[mt][nt][i] = 0.f;

    float4 avp[4], bvp[4];

    /* prologue: fetch tile k0=0 into registers */
#pragma unroll
    for (int c4 = 0; c4 < 4; c4++)
        avp[c4] = *(const float4*)(A + (size_t)(bm + arow) * K + acol0 + c4 * 8);
#pragma unroll
    for (int r = 0; r < 4; r++)
        bvp[r] = *(const float4*)(B + (size_t)(brow0 + r * 8) * N + bn + bcol);

    for (int k0 = 0; k0 < K; k0 += 32) {
        /* store current registers to SMEM (with tf32 convert) */
#pragma unroll
        for (int c4 = 0; c4 < 4; c4++) {
            const int kc = acol0 + c4 * 8;
            As[kc + 0][arow] = f2tf32(avp[c4].x);
            As[kc + 1][arow] = f2tf32(avp[c4].y);
            As[kc + 2][arow] = f2tf32(avp[c4].z);
            As[kc + 3][arow] = f2tf32(avp[c4].w);
        }
#pragma unroll
        for (int r = 0; r < 4; r++) {
            const int kr = brow0 + r * 8;
            Bs[kr][bcol + 0] = f2tf32(bvp[r].x);
            Bs[kr][bcol + 1] = f2tf32(bvp[r].y);
            Bs[kr][bcol + 2] = f2tf32(bvp[r].z);
            Bs[kr][bcol + 3] = f2tf32(bvp[r].w);
        }
        __syncthreads();

        /* prefetch NEXT tile into registers (overlaps with MMAs below) */
        const int k1 = k0 + 32;
        if (k1 < K) {
#pragma unroll
            for (int c4 = 0; c4 < 4; c4++)
                avp[c4] = *(const float4*)(A + (size_t)(bm + arow) * K + k1 + acol0 + c4 * 8);
#pragma unroll
            for (int r = 0; r < 4; r++)
                bvp[r] = *(const float4*)(B + (size_t)(k1 + brow0 + r * 8) * N + bn + bcol);
        }

#pragma unroll
        for (int kk = 0; kk < 4; kk++) {
            const int kb = kk * 8;
            unsigned af[4][4], bf[4][2];
#pragma unroll
            for (int mt = 0; mt < 4; mt++) {
                const int m = wm + mt * 16 + g;
                af[mt][0] = As[kb + tg][m];
                af[mt][1] = As[kb + tg][m + 8];
                af[mt][2] = As[kb + tg + 4][m];
                af[mt][3] = As[kb + tg + 4][m + 8];
            }
#pragma unroll
            for (int nt = 0; nt < 4; nt++) {
                const int n = wn + nt * 8 + g;
                bf[nt][0] = Bs[kb + tg][n];
                bf[nt][1] = Bs[kb + tg + 4][n];
            }
#pragma unroll
            for (int mt = 0; mt < 4; mt++)
#pragma unroll
                for (int nt = 0; nt < 4; nt++) {
                    asm volatile(
                        "mma.sync.aligned.m16n8k8.row.col.f32.tf32.tf32.f32 "
                        "{%0,%1,%2,%3}, {%4,%5,%6,%7}, {%8,%9}, {%0,%1,%2,%3};"
                        : "+f"(c[mt][nt][0]), "+f"(c[mt][nt][1]),
                          "+f"(c[mt][nt][2]), "+f"(c[mt][nt][3])
                        : "r"(af[mt][0]), "r"(af[mt][1]),
                          "r"(af[mt][2]), "r"(af[mt][3]),
                          "r"(bf[nt][0]), "r"(bf[nt][1]));
                }
        }
        __syncthreads();
    }

#pragma unroll
    for (int mt = 0; mt < 4; mt++) {
        const int m = bm + wm + mt * 16 + g;
#pragma unroll
        for (int nt = 0; nt < 4; nt++) {
            const int n = bn + wn + nt * 8 + 2 * tg;
            float2 lo = make_float2(c[mt][nt][0], c[mt][nt][1]);
            float2 hi = make_float2(c[mt][nt][2], c[mt][nt][3]);
            *(float2*)(C + (size_t)m * N + n)       = lo;
            *(float2*)(C + (size_t)(m + 8) * N + n) = hi;
        }
    }
}

/* --------------------------- LayerNorm + ReLU ------------------------------ */
__device__ __forceinline__ float block_reduce_sum_256(float v, float* red) {
#pragma unroll
    for (int off = 16; off; off >>= 1) v += __shfl_xor_sync(0xffffffffu, v, off);
    const int lane = threadIdx.x & 31, w = threadIdx.x >> 5;
    if (lane == 0) red[w] = v;
    __syncthreads();
    if (threadIdx.x < 32) {
        float r = (threadIdx.x < 8) ? red[threadIdx.x] : 0.f;
#pragma unroll
        for (int off = 4; off; off >>= 1) r += __shfl_xor_sync(0xffffffffu, r, off);
        if (threadIdx.x == 0) red[0] = r;
    }
    __syncthreads();
    float out = red[0];
    __syncthreads();
    return out;
}

__global__ __launch_bounds__(256)
void ln_relu_kernel(const float* __restrict__ X, const float* __restrict__ bias,
                    const float* __restrict__ scale, const float* __restrict__ beta,
                    float* __restrict__ Y) {
    __shared__ float red[8];
    const int row = blockIdx.x, tid = threadIdx.x;
    float4 x = ((const float4*)(X + (size_t)row * HDIM))[tid];
    float4 b = ((const float4*)bias)[tid];
    x.x += b.x; x.y += b.y; x.z += b.z; x.w += b.w;

    float s   = x.x + x.y + x.z + x.w;
    float mu  = block_reduce_sum_256(s, red) * (1.f / HDIM);
    float dx0 = x.x - mu, dx1 = x.y - mu, dx2 = x.z - mu, dx3 = x.w - mu;
    float sq  = dx0 * dx0 + dx1 * dx1 + dx2 * dx2 + dx3 * dx3;
    float var = block_reduce_sum_256(sq, red) * (1.f / HDIM);
    float inv = rsqrtf(var + 1e-6f);

    float4 g = ((const float4*)scale)[tid];
    float4 t = ((const float4*)beta)[tid];
    float4 y;
    y.x = fmaxf(fmaf(dx0 * inv, g.x, t.x), 0.f);
    y.y = fmaxf(fmaf(dx1 * inv, g.y, t.y), 0.f);
    y.z = fmaxf(fmaf(dx2 * inv, g.z, t.z), 0.f);
    y.w = fmaxf(fmaf(dx3 * inv, g.w, t.w), 0.f);
    ((float4*)(Y + (size_t)row * HDIM))[tid] = y;
}

/* ------------------------------ head epilogue ------------------------------ */
__device__ __forceinline__ float exp_sigmoid_f(float x) {
    float s = 1.f / (1.f + expf(-x));
    return 2.f * powf(s, 2.302585093f) + 1e-7f;
}

__global__ __launch_bounds__(128)
void head_epilogue(const float* __restrict__ head, const float* __restrict__ amp_b,
                   const float* __restrict__ harm_b, const float* __restrict__ noise_b,
                   float* __restrict__ out) {
    __shared__ float red[4];
    __shared__ float s_amp;
    const int row = blockIdx.x, tid = threadIdx.x;
    const float* hr = head + (size_t)row * 256;

    float myh = 0.f;
    if (tid < 100) myh = exp_sigmoid_f(hr[1 + tid] + harm_b[tid]);

    float s = myh;
#pragma unroll
    for (int off = 16; off; off >>= 1) s += __shfl_xor_sync(0xffffffffu, s, off);
    if ((tid & 31) == 0) red[tid >> 5] = s;
    __syncthreads();
    if (tid == 0) {
        float tot = red[0] + red[1] + red[2] + red[3];
        float amp = exp_sigmoid_f(hr[0] + amp_b[0]);
        s_amp = amp / (tot + 1e-8f);
    }
    __syncthreads();

    if (tid < 100)
        out[(size_t)row * 100 + tid] = s_amp * myh;
    if (tid < 65)
        out[(size_t)T_STEPS * 100 + (size_t)row * 65 + tid] = hr[101 + tid] + noise_b[tid];
}

/* -------------------------------- launcher --------------------------------- */
extern "C" void kernel_launch(void* const* d_in, const int* in_sizes, int n_in,
                              void* d_out, int out_size) {
    const float* f0       = (const float*)d_in[0];
    const float* loud     = (const float*)d_in[1];
    const float* W_in     = (const float*)d_in[2];
    const float* b_in     = (const float*)d_in[3];
    const float* Wi       = (const float*)d_in[4];
    const float* Wh       = (const float*)d_in[5];
    const float* b_h      = (const float*)d_in[6];
    const float* h0       = (const float*)d_in[7];
    const float* mlp_W    = (const float*)d_in[8];
    const float* mlp_b    = (const float*)d_in[9];
    const float* ln_scale = (const float*)d_in[10];
    const float* ln_bias  = (const float*)d_in[11];
    const float* amp_W    = (const float*)d_in[12];
    const float* amp_b    = (const float*)d_in[13];
    const float* harm_W   = (const float*)d_in[14];
    const float* harm_b   = (const float*)d_in[15];
    const float* noise_W  = (const float*)d_in[16];
    const float* noise_b  = (const float*)d_in[17];
    float* out = (float*)d_out;

    /* reset mailbox tags for graph-replay determinism */
    void* mbAddr = nullptr;
    cudaGetSymbolAddress(&mbAddr, g_mbox);
    cudaMemsetAsync(mbAddr, 0, 2 * NCOPY * HDIM * sizeof(unsigned long long), 0);

    float *hseq, *p1, *p2, *wp, *headb;
    cudaGetSymbolAddress((void**)&hseq,  g_hseq);
    cudaGetSymbolAddress((void**)&p1,    g_buf1);
    cudaGetSymbolAddress((void**)&p2,    g_buf2);
    cudaGetSymbolAddress((void**)&wp,    g_Wp);
    cudaGetSymbolAddress((void**)&headb, g_head);

    transpose_wh<<<dim3(96, 32), dim3(32, 8)>>>(Wh);
    a012_kernel<<<12, 256>>>(W_in, b_in, Wi);
    pack_heads<<<1024, 256>>>(amp_W, harm_W, noise_W);

    gru_kernel<<<NCTA, 256>>>(f0, loud, b_h, h0);

    /* MLP: 3 x (TF32 tensor GEMM -> LN+ReLU) */
    tf32gemm128<<<dim3(HDIM / 128, T_STEPS / 128), 256>>>(hseq, mlp_W, p1, T_STEPS, HDIM, HDIM);
    ln_relu_kernel<<<T_STEPS, 256>>>(p1, mlp_b, ln_scale, ln_bias, p2);

    tf32gemm128<<<dim3(HDIM / 128, T_STEPS / 128), 256>>>(p2, mlp_W + HDIM * HDIM, p1, T_STEPS, HDIM, HDIM);
    ln_relu_kernel<<<T_STEPS, 256>>>(p1, mlp_b + HDIM, ln_scale + HDIM, ln_bias + HDIM, p2);

    tf32gemm128<<<dim3(HDIM / 128, T_STEPS / 128), 256>>>(p2, mlp_W + 2 * HDIM * HDIM, p1, T_STEPS, HDIM, HDIM);
    ln_relu_kernel<<<T_STEPS, 256>>>(p1, mlp_b + 2 * HDIM, ln_scale + 2 * HDIM, ln_bias + 2 * HDIM, p2);

    /* heads: [T,1024] @ [1024,256(packed)] on tensor cores too (N=256 = 2 tiles) */
    tf32gemm128<<<dim3(256 / 128, T_STEPS / 128), 256>>>(p2, wp, headb, T_STEPS, 256, HDIM);
    head_epilogue<<<T_STEPS, 128>>>(headb, amp_b, harm_b, noise_b, out);
}